// round 8
// baseline (speedup 1.0000x reference)
#include <cuda_runtime.h>
#include <math.h>

#define HDIM 1024
#define LDIM 512
#define VDIM 50257
#define NB   148
#define NT   1024
#define NWARPS (NB * 32)   // 4736, same as before

// ---------------- device scratch (no allocations allowed) ----------------
__device__ float g_attn[LDIM];
__device__ float g_wctx[HDIM];
__device__ float g_vout[HDIM];
__device__ float g_gh[3 * HDIM];
__device__ float g_hnew[HDIM];
__device__ float g_logits[VDIM];
__device__ float g_expsum;
__device__ unsigned g_bar_cnt = 0;
__device__ volatile unsigned g_bar_gen = 0;

// ---------------- software grid barrier (148 blocks, all co-resident) ----
__device__ __forceinline__ void grid_barrier() {
    __syncthreads();
    if (threadIdx.x == 0) {
        unsigned gen = g_bar_gen;
        __threadfence();
        unsigned t = atomicAdd(&g_bar_cnt, 1u);
        if (t == NB - 1) {
            g_bar_cnt = 0;
            __threadfence();
            g_bar_gen = gen + 1;
        } else {
            while (g_bar_gen == gen) __nanosleep(64);
        }
        __threadfence();
    }
    __syncthreads();
}

__device__ __forceinline__ float warpReduce(float v) {
    #pragma unroll
    for (int o = 16; o; o >>= 1) v += __shfl_down_sync(0xffffffffu, v, o);
    return v;
}

__global__ void __launch_bounds__(NT, 1)
fused_decoder(const int* __restrict__ x, const float* __restrict__ hidden,
              const float* __restrict__ enc, const float* __restrict__ emb,
              const float* __restrict__ Ww, const float* __restrict__ bw,
              const float* __restrict__ Wc, const float* __restrict__ bc,
              const float* __restrict__ Wih, const float* __restrict__ Whh,
              const float* __restrict__ bih, const float* __restrict__ bhh,
              const float* __restrict__ Wo, const float* __restrict__ bo,
              float* __restrict__ out) {
    __shared__ float sbuf[2048];        // staged vectors (as float4[512])
    __shared__ float sred[1024];
    __shared__ float swarp[32];
    __shared__ float s_m, s_inv;

    const int blk = blockIdx.x, t = threadIdx.x;
    const int warp = t >> 5, lane = t & 31;
    float4* sb4 = (float4*)sbuf;

    // virtual 256-thread block id (matches R4 mapping)
    const int vblk = blk * 4 + (warp >> 3);   // 0..591
    const int vwarp = warp & 7;               // 0..7

    // ================= Phase 1: attn logits + gh = Whh@h + bhh ============
    {
        const float4* e4 = (const float4*)(emb + (size_t)x[0] * HDIM);
        const float4* h4 = (const float4*)hidden;
        if (t < 256) sb4[t] = e4[t];
        else if (t < 512) sb4[t] = h4[t - 256];
        if (blk == 16 && t < HDIM) g_wctx[t] = 0.f;
        if (blk == 16 && t == 0) g_expsum = 0.f;
        __syncthreads();
        if (vblk < 64) {
            // attention row: 2048-dot against [emb, hidden]
            int row = vblk * 8 + vwarp;
            const float4* w4 = (const float4*)Ww + (size_t)row * 512;
            float acc = 0.f;
            #pragma unroll
            for (int k = 0; k < 16; k++) {
                int idx = k * 32 + lane;
                float4 a = w4[idx], b = sb4[idx];
                acc += a.x * b.x + a.y * b.y + a.z * b.z + a.w * b.w;
            }
            acc = warpReduce(acc);
            if (lane == 0) g_attn[row] = acc + bw[row];
        } else {
            // gh row: 1024-dot against hidden
            int gw = (vblk - 64) * 8 + vwarp;   // 0..4223
            if (gw < 3 * HDIM) {
                const float4* w4 = (const float4*)Whh + (size_t)gw * 256;
                float acc = 0.f;
                #pragma unroll
                for (int k = 0; k < 8; k++) {
                    int idx = k * 32 + lane;
                    float4 a = w4[idx], b = sb4[256 + idx];
                    acc += a.x * b.x + a.y * b.y + a.z * b.z + a.w * b.w;
                }
                acc = warpReduce(acc);
                if (lane == 0) g_gh[gw] = acc + bhh[gw];
            }
        }
    }
    grid_barrier();

    // ================= Phase 2: softmax (once per SM) + wctx ==============
    {
        if (t < 512) sbuf[t] = __ldcg(g_attn + t);
        __syncthreads();
        if (t < 512) sred[t] = sbuf[t];
        __syncthreads();
        #pragma unroll
        for (int o = 256; o; o >>= 1) { if (t < o) sred[t] = fmaxf(sred[t], sred[t + o]); __syncthreads(); }
        if (t == 0) s_m = sred[0];
        __syncthreads();
        float m = s_m;
        if (t < 512) sred[t] = expf(sbuf[t] - m);
        __syncthreads();
        #pragma unroll
        for (int o = 256; o; o >>= 1) { if (t < o) sred[t] += sred[t + o]; __syncthreads(); }
        if (t == 0) s_inv = 1.f / sred[0];
        __syncthreads();
        float inv = s_inv;

        // wctx: 37 L-chunks x 4 col-chunks over 148 blocks
        int lch = blk >> 2, c = blk & 3;
        int l0 = lch * 14;
        int ln = min(14, LDIM - l0);
        int col = c * 256 + (t & 255);
        int sub = t >> 8;
        float acc = 0.f;
        for (int j = sub; j < ln; j += 4)
            acc += expf(sbuf[l0 + j] - m) * enc[(size_t)(l0 + j) * HDIM + col];
        sred[t] = acc * inv;
        __syncthreads();
        if (t < 256)
            atomicAdd(&g_wctx[col], sred[t] + sred[t + 256] + sred[t + 512] + sred[t + 768]);

        if (blk == 0 && t < 512)   // weights output
            out[VDIM + HDIM + t] = expf(sbuf[t] - m) * inv;
    }
    grid_barrier();

    // ================= Phase 3: vout = relu(Wc @ [emb, wctx] + bc) ========
    {
        const float4* e4 = (const float4*)(emb + (size_t)x[0] * HDIM);
        if (t < 256) sb4[t] = e4[t];
        else if (t < 512) sb4[t] = __ldcg((const float4*)g_wctx + (t - 256));
        __syncthreads();
        if (blk < 128 && (warp & 3) == 0) {
            int row = blk * 8 + (warp >> 2);   // 0..1023
            const float4* w4 = (const float4*)Wc + (size_t)row * 512;
            float acc = 0.f;
            #pragma unroll
            for (int k = 0; k < 16; k++) {
                int idx = k * 32 + lane;
                float4 a = w4[idx], b = sb4[idx];
                acc += a.x * b.x + a.y * b.y + a.z * b.z + a.w * b.w;
            }
            acc = warpReduce(acc);
            if (lane == 0) g_vout[row] = fmaxf(acc + bc[row], 0.f);
        }
    }
    grid_barrier();

    // ================= Phase 4: GRU gates + h_new =========================
    {
        if (t < 256) sb4[t] = __ldcg((const float4*)g_vout + t);
        __syncthreads();
        if (blk < 128 && (warp & 3) == 0) {
            int i = blk * 8 + (warp >> 2);     // 0..1023
            const float4* wr = (const float4*)Wih + (size_t)i * 256;
            const float4* wz = (const float4*)Wih + (size_t)(i + HDIM) * 256;
            const float4* wn = (const float4*)Wih + (size_t)(i + 2 * HDIM) * 256;
            float a0 = 0.f, a1 = 0.f, a2 = 0.f;
            #pragma unroll
            for (int k = 0; k < 8; k++) {
                int idx = k * 32 + lane;
                float4 b = sb4[idx];
                float4 m0 = wr[idx]; a0 += m0.x * b.x + m0.y * b.y + m0.z * b.z + m0.w * b.w;
                float4 m1 = wz[idx]; a1 += m1.x * b.x + m1.y * b.y + m1.z * b.z + m1.w * b.w;
                float4 m2 = wn[idx]; a2 += m2.x * b.x + m2.y * b.y + m2.z * b.z + m2.w * b.w;
            }
            a0 = warpReduce(a0); a1 = warpReduce(a1); a2 = warpReduce(a2);
            if (lane == 0) {
                float gh_r = __ldcg(&g_gh[i]);
                float gh_z = __ldcg(&g_gh[i + HDIM]);
                float gh_n = __ldcg(&g_gh[i + 2 * HDIM]);
                float gi_r = a0 + bih[i];
                float gi_z = a1 + bih[i + HDIM];
                float gi_n = a2 + bih[i + 2 * HDIM];
                float r = 1.f / (1.f + expf(-(gi_r + gh_r)));
                float z = 1.f / (1.f + expf(-(gi_z + gh_z)));
                float n = tanhf(gi_n + r * gh_n);
                float hn = (1.f - z) * n + z * hidden[i];
                g_hnew[i] = hn;
                out[VDIM + i] = hn;
            }
        }
    }
    grid_barrier();

    // ================= Phase 5: vocab GEMV + exp-sum (R4 structure) =======
    {
        if (t < 256) sb4[t] = __ldcg((const float4*)g_hnew + t);
        __syncthreads();
        int g = blk * 32 + warp;               // 0..4735
        float esum = 0.f;
        for (int r = g; r < VDIM; r += 2 * NWARPS) {
            int rB = r + NWARPS;
            bool vB = rB < VDIM;
            const float4* wA = (const float4*)Wo + (size_t)r * 256;
            const float4* wB = (const float4*)Wo + (size_t)rB * 256;
            float accA = 0.f, accB = 0.f;
            #pragma unroll
            for (int k = 0; k < 8; k++) {
                int idx = k * 32 + lane;
                float4 b = sb4[idx];
                float4 a = wA[idx];
                accA += a.x * b.x + a.y * b.y + a.z * b.z + a.w * b.w;
                if (vB) {
                    float4 a2 = wB[idx];
                    accB += a2.x * b.x + a2.y * b.y + a2.z * b.z + a2.w * b.w;
                }
            }
            accA = warpReduce(accA);
            accB = warpReduce(accB);
            if (lane == 0) {
                float lA = accA + bo[r];
                g_logits[r] = lA;
                esum += expf(lA);
                if (vB) {
                    float lB = accB + bo[rB];
                    g_logits[rB] = lB;
                    esum += expf(lB);
                }
            }
        }
        if (lane == 0) swarp[warp] = esum;
        __syncthreads();
        if (t == 0) {
            float s = 0.f;
            #pragma unroll
            for (int w = 0; w < 32; w++) s += swarp[w];
            atomicAdd(&g_expsum, s);
        }
    }
    grid_barrier();

    // ================= Phase 6: log_softmax write ==========================
    {
        float lse = logf(__ldcg(&g_expsum));
        int v = blk * NT + t;
        if (v < VDIM) out[v] = __ldcg(&g_logits[v]) - lse;
    }
}

// ---------------------------------------------------------------------------
extern "C" void kernel_launch(void* const* d_in, const int* in_sizes, int n_in,
                              void* d_out, int out_size) {
    const int*   x      = (const int*)  d_in[0];
    const float* hidden = (const float*)d_in[1];
    const float* enc    = (const float*)d_in[2];
    const float* emb    = (const float*)d_in[3];
    const float* Ww     = (const float*)d_in[4];
    const float* bw     = (const float*)d_in[5];
    const float* Wc     = (const float*)d_in[6];
    const float* bc     = (const float*)d_in[7];
    const float* Wih    = (const float*)d_in[8];
    const float* Whh    = (const float*)d_in[9];
    const float* bih    = (const float*)d_in[10];
    const float* bhh    = (const float*)d_in[11];
    const float* Wo     = (const float*)d_in[12];
    const float* bo     = (const float*)d_in[13];
    float* out = (float*)d_out;

    fused_decoder<<<NB, NT>>>(x, hidden, enc, emb, Ww, bw, Wc, bc,
                              Wih, Whh, bih, bhh, Wo, bo, out);
}